// round 10
// baseline (speedup 1.0000x reference)
#include <cuda_runtime.h>
#include <cuda_bf16.h>
#include <cstdint>

#define D_MODEL 2048
#define RANK    64
#define VOCAB   50257
#define N_TOK   32

#define NBLK_PART 32

#define TILE       256                      // columns per tile (= threads/block)
#define GRID_OUTER 148                      // persistent: 1 block/SM
#define NTILES     ((VOCAB + TILE - 1) / TILE)   // 197
#define STAGE_FLOATS (RANK * TILE)          // 16384 floats = 64KB per stage

__device__ float g_part[NBLK_PART * N_TOK];
__device__ float g_s[N_TOK];
__device__ int   g_count;

// Kernel 1: s[n] = sum_d h[n,d] * (sum_r U[d,r]*S[r]); last block folds.
__global__ __launch_bounds__(256)
void fftlm_partial_kernel(const float* __restrict__ h,
                          const float* __restrict__ U,
                          const float* __restrict__ S) {
    __shared__ float sS[RANK];
    __shared__ float su[64];
    __shared__ int   is_last;

    const int tid  = threadIdx.x;
    const int warp = tid >> 5;
    const int lane = tid & 31;
    const int dbase = blockIdx.x * 64;

    if (tid < RANK) sS[tid] = S[tid];
    __syncthreads();

#pragma unroll
    for (int k = 0; k < 8; k++) {
        int dl = warp * 8 + k;
        const float* Ur = U + (size_t)(dbase + dl) * RANK;
        float v = Ur[lane] * sS[lane] + Ur[lane + 32] * sS[lane + 32];
#pragma unroll
        for (int o = 16; o; o >>= 1) v += __shfl_xor_sync(0xffffffffu, v, o);
        if (lane == 0) su[dl] = v;
    }
    __syncthreads();

#pragma unroll
    for (int k = 0; k < 4; k++) {
        int n = warp * 4 + k;
        const float* hr = h + (size_t)n * D_MODEL + dbase;
        float v = hr[lane] * su[lane] + hr[lane + 32] * su[lane + 32];
#pragma unroll
        for (int o = 16; o; o >>= 1) v += __shfl_xor_sync(0xffffffffu, v, o);
        if (lane == 0) g_part[blockIdx.x * N_TOK + n] = v;
    }

    __threadfence();
    if (tid == 0) is_last = (atomicAdd(&g_count, 1) == NBLK_PART - 1);
    __syncthreads();
    if (is_last) {
        if (tid < N_TOK) {
            float acc = 0.f;
#pragma unroll
            for (int b = 0; b < NBLK_PART; b++) acc += g_part[b * N_TOK + tid];
            g_s[tid] = acc;
        }
        if (tid == 0) g_count = 0;   // self-reset for graph replay
    }
}

// Kernel 2: out[n,v] = s[n] * sum_r Vh[r,v], cp.async-pipelined.
// Loads bypass registers entirely (LDGSTS -> smem); each thread posts 64
// 4B copies per tile, consumes ONLY its own column (no block sync needed).
__global__ __launch_bounds__(TILE)
void fftlm_outer_kernel(const float* __restrict__ Vh,
                        float* __restrict__ out) {
    extern __shared__ float stage[];          // 2 * STAGE_FLOATS
    __shared__ float s_sh[N_TOK];
    const int tid = threadIdx.x;
    if (tid < N_TOK) s_sh[tid] = g_s[tid];
    __syncthreads();

    const uint32_t smem_base =
        (uint32_t)__cvta_generic_to_shared(stage) + (uint32_t)tid * 4u;

    // post all 64 row-copies for one tile into stage st (predicated per thread)
    auto issue = [&](int tile, int st) {
        if (tile < NTILES) {
            const int col = tile * TILE + tid;
            if (col < VOCAB) {
                const float* src = Vh + col;
                uint32_t dst = smem_base + (uint32_t)st * (STAGE_FLOATS * 4u);
#pragma unroll
                for (int r = 0; r < RANK; r++) {
                    asm volatile("cp.async.ca.shared.global [%0], [%1], 4;"
                                 :: "r"(dst), "l"(src));
                    src += VOCAB;
                    dst += TILE * 4u;
                }
            }
        }
        asm volatile("cp.async.commit_group;" ::: "memory");
    };

    issue(blockIdx.x, 0);
    issue(blockIdx.x + GRID_OUTER, 1);

    int i = 0;
    for (int tile = blockIdx.x; tile < NTILES; tile += GRID_OUTER, i++) {
        asm volatile("cp.async.wait_group 1;" ::: "memory");
        const int st  = i & 1;
        const int col = tile * TILE + tid;
        if (col < VOCAB) {
            const float* buf = stage + st * STAGE_FLOATS + tid;
            float a0 = 0.f, a1 = 0.f, a2 = 0.f, a3 = 0.f;
#pragma unroll
            for (int r = 0; r < RANK; r += 4) {        // conflict-free: bank=lane
                a0 += buf[(r + 0) * TILE];
                a1 += buf[(r + 1) * TILE];
                a2 += buf[(r + 2) * TILE];
                a3 += buf[(r + 3) * TILE];
            }
            const float acc = (a0 + a1) + (a2 + a3);
            float* q = out + col;
#pragma unroll
            for (int n = 0; n < N_TOK; n++)
                q[(size_t)n * VOCAB] = s_sh[n] * acc;
        }
        issue(tile + 2 * GRID_OUTER, st);   // refill the stage just consumed
    }
    asm volatile("cp.async.wait_group 0;" ::: "memory");
}

extern "C" void kernel_launch(void* const* d_in, const int* in_sizes, int n_in,
                              void* d_out, int out_size) {
    const float* h  = (const float*)d_in[0];  // (32, 2048)
    const float* U  = (const float*)d_in[1];  // (2048, 64)
    const float* S  = (const float*)d_in[2];  // (64,)
    const float* Vh = (const float*)d_in[3];  // (64, 50257)
    float* out = (float*)d_out;               // (32, 50257)

    // idempotent, host-side, not a stream op — safe to call every time
    // (no static guard: kernel_launch must behave identically on every call)
    cudaFuncSetAttribute(fftlm_outer_kernel,
                         cudaFuncAttributeMaxDynamicSharedMemorySize,
                         2 * STAGE_FLOATS * sizeof(float));

    fftlm_partial_kernel<<<NBLK_PART, 256>>>(h, U, S);
    fftlm_outer_kernel<<<GRID_OUTER, TILE,
                         2 * STAGE_FLOATS * sizeof(float)>>>(Vh, out);
}

// round 13
// speedup vs baseline: 1.1662x; 1.1662x over previous
#include <cuda_runtime.h>
#include <cuda_bf16.h>
#include <cstdint>

#define D_MODEL 2048
#define RANK    64
#define VOCAB   50257
#define N_TOK   32

#define NPART     32
#define TILE_C    1024
#define NTC       ((VOCAB + TILE_C - 1) / TILE_C)   // 50
#define NRG       4                                  // row groups of 16 rows
#define NCOL_BLK  (NTC * NRG)                        // 200
#define GRID_A    (NCOL_BLK + NPART)                 // 232

__device__ float g_part[NPART * N_TOK];
__device__ float g_s[N_TOK];
__device__ float g_w[NRG * VOCAB];     // per-row-group column partials (804KB)
__device__ int   g_count;              // self-resetting

// Kernel A: (a) column partial sums with DRAM-friendly contiguous 4KB bursts,
//           (b) partial s[n] in the extra 32 blocks (last one folds -> g_s).
__global__ __launch_bounds__(256)
void fftlm_colsum_kernel(const float* __restrict__ h,
                         const float* __restrict__ U,
                         const float* __restrict__ S,
                         const float* __restrict__ Vh) {
    const int bid = blockIdx.x;
    const int tid = threadIdx.x;

    if (bid < NCOL_BLK) {
        // ---- column-sum tile: rows [rg*16, rg*16+16), cols [c0, c0+1024) ----
        const int rg = bid & 3;
        const int c0 = (bid >> 2) * TILE_C;
        const int r0 = rg * 16;
        const float* base = Vh + (size_t)r0 * VOCAB + c0 + tid;

        float acc0 = 0.f, acc1 = 0.f, acc2 = 0.f, acc3 = 0.f;

        if (c0 + TILE_C <= VOCAB) {
            // full tile: each 4-row step streams 16 independent loads;
            // per row the block touches 4KB CONTIGUOUS (DRAM page friendly)
#pragma unroll
            for (int rr = 0; rr < 16; rr += 4) {
                const float* p = base + (size_t)rr * VOCAB;
                float b[16];
#pragma unroll
                for (int j = 0; j < 4; j++)
#pragma unroll
                    for (int k = 0; k < 4; k++)
                        b[j * 4 + k] = p[(size_t)j * VOCAB + k * 256];
                acc0 += (b[0] + b[4]) + (b[8]  + b[12]);
                acc1 += (b[1] + b[5]) + (b[9]  + b[13]);
                acc2 += (b[2] + b[6]) + (b[10] + b[14]);
                acc3 += (b[3] + b[7]) + (b[11] + b[15]);
            }
            float* w = g_w + (size_t)rg * VOCAB + c0 + tid;
            w[0]   = acc0;
            w[256] = acc1;
            w[512] = acc2;
            w[768] = acc3;
        } else {
            // tail tile (cols 50176..50256)
            const bool ok0 = (c0 + tid        ) < VOCAB;
            const bool ok1 = (c0 + tid + 256  ) < VOCAB;
            const bool ok2 = (c0 + tid + 512  ) < VOCAB;
            const bool ok3 = (c0 + tid + 768  ) < VOCAB;
            for (int rr = 0; rr < 16; rr++) {
                const float* p = base + (size_t)rr * VOCAB;
                if (ok0) acc0 += p[0];
                if (ok1) acc1 += p[256];
                if (ok2) acc2 += p[512];
                if (ok3) acc3 += p[768];
            }
            float* w = g_w + (size_t)rg * VOCAB + c0 + tid;
            if (ok0) w[0]   = acc0;
            if (ok1) w[256] = acc1;
            if (ok2) w[512] = acc2;
            if (ok3) w[768] = acc3;
        }
        return;
    }

    // ---- partial s[n] (32 blocks); last block folds into g_s ----
    {
        __shared__ float sS[RANK];
        __shared__ float su[64];
        __shared__ int   is_last;
        const int warp = tid >> 5, lane = tid & 31;
        const int dbase = (bid - NCOL_BLK) * 64;

        if (tid < RANK) sS[tid] = S[tid];
        __syncthreads();
#pragma unroll
        for (int k = 0; k < 8; k++) {
            int dl = warp * 8 + k;
            const float* Ur = U + (size_t)(dbase + dl) * RANK;
            float v = Ur[lane] * sS[lane] + Ur[lane + 32] * sS[lane + 32];
#pragma unroll
            for (int o = 16; o; o >>= 1) v += __shfl_xor_sync(0xffffffffu, v, o);
            if (lane == 0) su[dl] = v;
        }
        __syncthreads();
#pragma unroll
        for (int k = 0; k < 4; k++) {
            int n = warp * 4 + k;
            const float* hr = h + (size_t)n * D_MODEL + dbase;
            float v = hr[lane] * su[lane] + hr[lane + 32] * su[lane + 32];
#pragma unroll
            for (int o = 16; o; o >>= 1) v += __shfl_xor_sync(0xffffffffu, v, o);
            if (lane == 0) g_part[(bid - NCOL_BLK) * N_TOK + n] = v;
        }
        __threadfence();
        if (tid == 0) is_last = (atomicAdd(&g_count, 1) == NPART - 1);
        __syncthreads();
        if (is_last) {
            if (tid < N_TOK) {
                float acc = 0.f;
#pragma unroll
                for (int b = 0; b < NPART; b++) acc += g_part[b * N_TOK + tid];
                g_s[tid] = acc;
            }
            if (tid == 0) g_count = 0;   // self-reset for graph replay
        }
    }
}

// Kernel B: w[v] = sum_rg g_w[rg][v] (L2-hot), out[n,v] = s[n]*w[v].
// 256 threads = 2 half-blocks x 128 cols; each thread stores 16 token rows.
__global__ __launch_bounds__(256)
void fftlm_bcast_kernel(float* __restrict__ out) {
    __shared__ float s_sh[N_TOK];
    const int tid = threadIdx.x;
    if (tid < N_TOK) s_sh[tid] = g_s[tid];
    __syncthreads();

    const int tsub = tid >> 7;              // 0: tokens 0-15, 1: tokens 16-31
    const int col  = blockIdx.x * 128 + (tid & 127);
    if (col >= VOCAB) return;

    const float w = (g_w[col]             + g_w[VOCAB + col])
                  + (g_w[2 * VOCAB + col] + g_w[3 * VOCAB + col]);

    float sv[16];
#pragma unroll
    for (int j = 0; j < 16; j++) sv[j] = s_sh[tsub * 16 + j];

    float* q = out + (size_t)(tsub * 16) * VOCAB + col;
#pragma unroll
    for (int j = 0; j < 16; j++)
        q[(size_t)j * VOCAB] = sv[j] * w;
}

extern "C" void kernel_launch(void* const* d_in, const int* in_sizes, int n_in,
                              void* d_out, int out_size) {
    const float* h  = (const float*)d_in[0];  // (32, 2048)
    const float* U  = (const float*)d_in[1];  // (2048, 64)
    const float* S  = (const float*)d_in[2];  // (64,)
    const float* Vh = (const float*)d_in[3];  // (64, 50257)
    float* out = (float*)d_out;               // (32, 50257)

    fftlm_colsum_kernel<<<GRID_A, 256>>>(h, U, S, Vh);

    const int blocksB = (VOCAB + 127) / 128;  // 393
    fftlm_bcast_kernel<<<blocksB, 256>>>(out);
}

// round 14
// speedup vs baseline: 1.1768x; 1.0091x over previous
#include <cuda_runtime.h>
#include <cuda_bf16.h>
#include <cstdint>

#define D_MODEL 2048
#define RANK    64
#define VOCAB   50257
#define N_TOK   32

#define NPART     32
#define TILE_C    1792                               // 7 * 256
#define NTC       ((VOCAB + TILE_C - 1) / TILE_C)    // 29 (28 full + 81-col tail)
#define NRG       4                                  // row groups of 16 rows
#define NCOL_BLK  (NTC * NRG)                        // 116
#define GRID_A    (NCOL_BLK + NPART)                 // 148 = exactly 1 block/SM

__device__ float g_part[NPART * N_TOK];
__device__ float g_s[N_TOK];
__device__ float g_w[NRG * VOCAB];     // per-row-group column partials
__device__ int   g_count;              // self-resetting

// Kernel A (one wave, 148 blocks):
//   blocks [0,116): column partial sums, 16 rows x 1792 cols, 7KB contiguous
//   per row per block (DRAM-page friendly bursts).
//   blocks [116,148): partial s[n]; last one folds into g_s (counter, no spin).
__global__ __launch_bounds__(256)
void fftlm_colsum_kernel(const float* __restrict__ h,
                         const float* __restrict__ U,
                         const float* __restrict__ S,
                         const float* __restrict__ Vh) {
    const int bid = blockIdx.x;
    const int tid = threadIdx.x;

    if (bid < NCOL_BLK) {
        const int rg = bid & 3;
        const int c0 = (bid >> 2) * TILE_C;
        const int r0 = rg * 16;
        const float* base = Vh + (size_t)r0 * VOCAB + c0 + tid;

        float acc[7];
#pragma unroll
        for (int k = 0; k < 7; k++) acc[k] = 0.f;

        if (c0 + TILE_C <= VOCAB) {
            // full tile: 7 loads/row/thread, block covers 7KB contiguous per row
#pragma unroll
            for (int rr = 0; rr < 16; rr++) {
                const float* p = base + (size_t)rr * VOCAB;
                float b[7];
#pragma unroll
                for (int k = 0; k < 7; k++) b[k] = p[k * 256];
#pragma unroll
                for (int k = 0; k < 7; k++) acc[k] += b[k];
            }
            float* w = g_w + (size_t)rg * VOCAB + c0 + tid;
#pragma unroll
            for (int k = 0; k < 7; k++) w[k * 256] = acc[k];
        } else {
            // tail tile: cols 50176..50256 (81 cols)
            bool ok[7];
#pragma unroll
            for (int k = 0; k < 7; k++) ok[k] = (c0 + tid + k * 256) < VOCAB;
            for (int rr = 0; rr < 16; rr++) {
                const float* p = base + (size_t)rr * VOCAB;
#pragma unroll
                for (int k = 0; k < 7; k++) if (ok[k]) acc[k] += p[k * 256];
            }
            float* w = g_w + (size_t)rg * VOCAB + c0 + tid;
#pragma unroll
            for (int k = 0; k < 7; k++) if (ok[k]) w[k * 256] = acc[k];
        }
        return;
    }

    // ---- partial s[n] (32 blocks); last block folds into g_s ----
    {
        __shared__ float sS[RANK];
        __shared__ float su[64];
        __shared__ int   is_last;
        const int warp = tid >> 5, lane = tid & 31;
        const int dbase = (bid - NCOL_BLK) * 64;

        if (tid < RANK) sS[tid] = S[tid];
        __syncthreads();
#pragma unroll
        for (int k = 0; k < 8; k++) {
            int dl = warp * 8 + k;
            const float* Ur = U + (size_t)(dbase + dl) * RANK;
            float v = Ur[lane] * sS[lane] + Ur[lane + 32] * sS[lane + 32];
#pragma unroll
            for (int o = 16; o; o >>= 1) v += __shfl_xor_sync(0xffffffffu, v, o);
            if (lane == 0) su[dl] = v;
        }
        __syncthreads();
#pragma unroll
        for (int k = 0; k < 4; k++) {
            int n = warp * 4 + k;
            const float* hr = h + (size_t)n * D_MODEL + dbase;
            float v = hr[lane] * su[lane] + hr[lane + 32] * su[lane + 32];
#pragma unroll
            for (int o = 16; o; o >>= 1) v += __shfl_xor_sync(0xffffffffu, v, o);
            if (lane == 0) g_part[(bid - NCOL_BLK) * N_TOK + n] = v;
        }
        __threadfence();
        if (tid == 0) is_last = (atomicAdd(&g_count, 1) == NPART - 1);
        __syncthreads();
        if (is_last) {
            if (tid < N_TOK) {
                float acc = 0.f;
#pragma unroll
                for (int b = 0; b < NPART; b++) acc += g_part[b * N_TOK + tid];
                g_s[tid] = acc;
            }
            if (tid == 0) g_count = 0;   // self-reset for graph replay
        }
    }
}

// Kernel B: w[v] = sum_rg g_w[rg][v] (L2-hot); out[n,v] = s[n]*w[v].
// NO smem, NO syncthreads: w-loads issued first, g_s broadcast loads overlap,
// then 8 stores/thread. 786 blocks x 256 thr (~5.3 blocks/SM) for deep overlap.
__global__ __launch_bounds__(256)
void fftlm_bcast_kernel(float* __restrict__ out) {
    const int tid  = threadIdx.x;
    const int rg4  = tid >> 6;                       // 8-token group 0..3
    const int col  = blockIdx.x * 64 + (tid & 63);
    if (col >= VOCAB) return;

    // issue the 4 partial-w loads first (L2-resident after kernel A)
    const float w0 = g_w[col];
    const float w1 = g_w[VOCAB + col];
    const float w2 = g_w[2 * VOCAB + col];
    const float w3 = g_w[3 * VOCAB + col];

    // warp-uniform broadcast loads of this thread's 8 token scalars
    float sv[8];
#pragma unroll
    for (int j = 0; j < 8; j++) sv[j] = g_s[rg4 * 8 + j];

    const float w = (w0 + w1) + (w2 + w3);

    float* q = out + (size_t)(rg4 * 8) * VOCAB + col;
#pragma unroll
    for (int j = 0; j < 8; j++)
        q[(size_t)j * VOCAB] = sv[j] * w;
}

extern "C" void kernel_launch(void* const* d_in, const int* in_sizes, int n_in,
                              void* d_out, int out_size) {
    const float* h  = (const float*)d_in[0];  // (32, 2048)
    const float* U  = (const float*)d_in[1];  // (2048, 64)
    const float* S  = (const float*)d_in[2];  // (64,)
    const float* Vh = (const float*)d_in[3];  // (64, 50257)
    float* out = (float*)d_out;               // (32, 50257)

    fftlm_colsum_kernel<<<GRID_A, 256>>>(h, U, S, Vh);

    const int blocksB = (VOCAB + 63) / 64;    // 786
    fftlm_bcast_kernel<<<blocksB, 256>>>(out);
}